// round 14
// baseline (speedup 1.0000x reference)
#include <cuda_runtime.h>
#include <cuda_bf16.h>
#include <cstdint>

// ---------------------------------------------------------------------------
// GATModel on GB300: tcgen05 bf16 split-GEMM — persistent CTAs, occ=4
// (single 48KB stage buffer, <=64 regs via x16 epilogue), + two-phase GAT agg.
// R14: occupancy 2->4 on the GEMM (R13 profile: occ 22%, L2 55%, issue 8%).
// ---------------------------------------------------------------------------

#if defined(__CUDA_ARCH_FEAT_SM103_ALL) || defined(__CUDA_ARCH_FEAT_SM100_ALL) || \
    defined(__CUDA_ARCH_FEAT_SM101_ALL) || defined(__CUDA_ARCH_SPECIFIC__)
#define TC_OK 1
#else
#define TC_OK 0
#endif

#define NMAX 50000
#define EMAX 500000

__device__ float          g_buf1[NMAX * 256];
__device__ __nv_bfloat16  g_a_hi[NMAX * 256];
__device__ __nv_bfloat16  g_a_lo[NMAX * 256];
__device__ __nv_bfloat16  g_wb_hi[256 * 256];
__device__ __nv_bfloat16  g_wb_lo[256 * 256];
__device__ float g_ssrc[NMAX * 4];
__device__ float g_sdst[NMAX * 4];
__device__ int   g_counts[NMAX];
__device__ int   g_rowbeg[NMAX];
__device__ int   g_rowend[NMAX];
__device__ int   g_cursor[NMAX];
__device__ int   g_csrc[EMAX];
__device__ int   g_is64;
__device__ int   g_total;

// ---------------- edge_index dtype detection ----------------
__global__ void detect_dtype(const void* __restrict__ ei, int N) {
    const long long* p = (const long long*)ei;
    int ok = 1;
    for (int i = 0; i < 16; i++) {
        long long v = p[i];
        if (v < 0 || v >= (long long)N) ok = 0;
    }
    g_is64 = ok;
}
__device__ __forceinline__ int load_idx(const void* ei, long long pos) {
    if (g_is64) return (int)((const long long*)ei)[pos];
    return ((const int*)ei)[pos];
}

// ---------------- CSR build ----------------
__global__ void zero_counts(int N) {
    int i = blockIdx.x * blockDim.x + threadIdx.x;
    if (i < N) g_counts[i] = 0;
    if (i == 0) g_total = 0;
}
__global__ void hist_kernel(const void* __restrict__ ei, int E, int N) {
    int e = blockIdx.x * blockDim.x + threadIdx.x;
    if (e < E) {
        int d = load_idx(ei, (long long)E + e);
        if (d >= 0 && d < N) atomicAdd(&g_counts[d], 1);
    }
}
__global__ void __launch_bounds__(1024)
alloc_rows(int N) {
    __shared__ int sh[1024];
    __shared__ int sbase;
    int tid = threadIdx.x;
    int i = blockIdx.x * 1024 + tid;
    int c = (i < N) ? g_counts[i] : 0;
    sh[tid] = c;
    __syncthreads();
    for (int off = 1; off < 1024; off <<= 1) {
        int v = (tid >= off) ? sh[tid - off] : 0;
        __syncthreads();
        sh[tid] += v;
        __syncthreads();
    }
    if (tid == 1023) sbase = atomicAdd(&g_total, sh[1023]);
    __syncthreads();
    if (i < N) {
        int b = sbase + sh[tid] - c;
        g_rowbeg[i] = b;
        g_rowend[i] = b + c;
        g_cursor[i] = b;
    }
}
__global__ void scatter_kernel(const void* __restrict__ ei, int E, int N) {
    int e = blockIdx.x * blockDim.x + threadIdx.x;
    if (e < E) {
        int d = load_idx(ei, (long long)E + e);
        int s = load_idx(ei, e);
        if (d >= 0 && d < N && s >= 0 && s < N) {
            int pos = atomicAdd(&g_cursor[d], 1);
            if (pos >= 0 && pos < E) g_csrc[pos] = s;
        }
    }
}

// ---------------- fp32 -> bf16 hi/lo split conversions ----------------
__global__ void conv_split_x(const float* __restrict__ src, int n2) {
    int i = blockIdx.x * blockDim.x + threadIdx.x;
    if (i < n2) {
        float2 v = ((const float2*)src)[i];
        __nv_bfloat16 h0 = __float2bfloat16(v.x);
        __nv_bfloat16 h1 = __float2bfloat16(v.y);
        ((__nv_bfloat162*)g_a_hi)[i] = __halves2bfloat162(h0, h1);
        ((__nv_bfloat162*)g_a_lo)[i] = __halves2bfloat162(
            __float2bfloat16(v.x - __bfloat162float(h0)),
            __float2bfloat16(v.y - __bfloat162float(h1)));
    }
}
__global__ void conv_split_w(const float* __restrict__ src, int n2) {
    int i = blockIdx.x * blockDim.x + threadIdx.x;
    if (i < n2) {
        float2 v = ((const float2*)src)[i];
        __nv_bfloat16 h0 = __float2bfloat16(v.x);
        __nv_bfloat16 h1 = __float2bfloat16(v.y);
        ((__nv_bfloat162*)g_wb_hi)[i] = __halves2bfloat162(h0, h1);
        ((__nv_bfloat162*)g_wb_lo)[i] = __halves2bfloat162(
            __float2bfloat16(v.x - __bfloat162float(h0)),
            __float2bfloat16(v.y - __bfloat162float(h1)));
    }
}

// ---------------- tcgen05 helpers (arch-specific pass only) ----------------
#if TC_OK
__device__ __forceinline__ uint32_t elect_one_pred() {
    uint32_t pred;
    asm volatile("{\n\t.reg .pred p;\n\telect.sync _|p, 0xFFFFFFFF;\n\t"
                 "selp.b32 %0, 1, 0, p;\n\t}" : "=r"(pred));
    return pred;
}
__device__ __forceinline__ uint32_t smem_to_u32(const void* p) {
    uint32_t a;
    asm("{ .reg .u64 t; cvta.to.shared.u64 t, %1; cvt.u32.u64 %0, t; }"
        : "=r"(a) : "l"(p));
    return a;
}
#define MBARRIER_INIT(mbar, count) \
    asm volatile("mbarrier.init.shared.b64 [%0], %1;" \
                 :: "r"((uint32_t)(mbar)), "r"((uint32_t)(count)) : "memory")
#define MBARRIER_WAIT_PARITY(mbar, parity) do { \
    uint32_t _m = (uint32_t)(mbar), _p = (uint32_t)(parity), _d; \
    asm volatile("{\n\t.reg .pred p;\n\t" \
        "mbarrier.try_wait.parity.acquire.cta.shared::cta.b64 p, [%1], %2;\n\t" \
        "selp.b32 %0, 1, 0, p;\n\t}" : "=r"(_d) : "r"(_m), "r"(_p) : "memory"); \
    if (!_d) { \
        asm volatile("{\n\t.reg .pred P1;\n\t" \
            "WL_%=:\n\t" \
            "mbarrier.try_wait.parity.acquire.cta.shared::cta.b64 P1, [%0], %1, 0x989680;\n\t" \
            "@P1 bra.uni WD_%=;\n\tbra.uni WL_%=;\n\tWD_%=:\n\t}" \
            :: "r"(_m), "r"(_p) : "memory"); \
    } \
} while (0)
#define TCGEN05_ALLOC(sr, n) \
    asm volatile("tcgen05.alloc.cta_group::1.sync.aligned.shared::cta.b32 [%0], %1;" \
                 :: "r"((uint32_t)(sr)), "r"((uint32_t)(n)) : "memory")
#define TCGEN05_DEALLOC(t, n) \
    asm volatile("tcgen05.dealloc.cta_group::1.sync.aligned.b32 %0, %1;" \
                 :: "r"(t), "r"((uint32_t)(n)))
#define TCGEN05_RELINQ() \
    asm volatile("tcgen05.relinquish_alloc_permit.cta_group::1.sync.aligned;")
#define TCGEN05_COMMIT(mbar) \
    asm volatile("tcgen05.commit.cta_group::1.mbarrier::arrive::one.shared::cluster.b64 [%0];" \
                 :: "r"((uint32_t)(mbar)) : "memory")
#define TCGEN05_FENCE_AFTER() \
    asm volatile("tcgen05.fence::after_thread_sync;" ::: "memory")
#define TCGEN05_FENCE_BEFORE() \
    asm volatile("tcgen05.fence::before_thread_sync;" ::: "memory")
#define TCGEN05_WAIT_LD() \
    asm volatile("tcgen05.wait::ld.sync.aligned;" ::: "memory")
#define TCGEN05_LD_32X32B_X16(r, ta) \
    asm volatile("tcgen05.ld.sync.aligned.32x32b.x16.b32 " \
        "{%0, %1, %2, %3, %4, %5, %6, %7, %8, %9, %10, %11, %12, %13, %14, %15}, [%16];" \
        : "=r"((r)[0]), "=r"((r)[1]), "=r"((r)[2]), "=r"((r)[3]), \
          "=r"((r)[4]), "=r"((r)[5]), "=r"((r)[6]), "=r"((r)[7]), \
          "=r"((r)[8]), "=r"((r)[9]), "=r"((r)[10]), "=r"((r)[11]), \
          "=r"((r)[12]), "=r"((r)[13]), "=r"((r)[14]), "=r"((r)[15]) \
        : "r"(ta))
#define CP_ASYNC16(dst, src) \
    asm volatile("cp.async.cg.shared.global [%0], [%1], 16;" \
                 :: "r"((uint32_t)(dst)), "l"(src) : "memory")
#define CP_COMMIT() \
    asm volatile("cp.async.commit_group;" ::: "memory")
#define CP_WAIT_GROUP(n) \
    asm volatile("cp.async.wait_group %0;" :: "n"(n) : "memory")

__device__ __forceinline__ uint64_t make_desc(uint32_t addr) {
    uint64_t base = (uint64_t(2) << 61) | (uint64_t(1) << 46) |
                    (uint64_t(64) << 32) | (uint64_t(1) << 16);
    return base | ((uint64_t)(addr >> 4) & 0x3FFF);
}
__device__ __forceinline__ void mma_f16_ss(uint32_t d, uint64_t ad, uint64_t bd,
                                           uint32_t idesc, bool en) {
    uint32_t e = en ? 1u : 0u;
    asm volatile("{\n\t.reg .pred p;\n\tsetp.ne.u32 p, %5, 0;\n\t"
                 "tcgen05.mma.cta_group::1.kind::f16 [%0], %1, %2, %3, {%4, %4, %4, %4}, p;\n\t}"
                 :: "r"(d), "l"(ad), "l"(bd), "r"(idesc), "r"(0u), "r"(e)
                 : "memory");
}
#define MMA_IDESC 0x8100490u
#endif  // TC_OK

// ---------------- persistent tcgen05 split-GEMM, occ=4 ----------------
// Tiles: C[128,64]; 4 serial K-stages of 64 through ONE 48KB stage buffer.
// 592 persistent CTAs (4/SM); next tile's stage-0 load overlaps epilogue.
#define SM_TMEM 0
#define SM_MB0 8
#define SM_BUF 1024
#define OFF_ALO 16384
#define OFF_BHI 32768
#define OFF_BLO 40960
#define SM_TOTAL (1024 + 49152)
#define GEMM_GRID 592

__global__ void __launch_bounds__(256, 4)
gemm_tc(const float* __restrict__ bias,
        float* __restrict__ Cext, int toExt, int M, int Nout,
        const float* __restrict__ a_src, const float* __restrict__ a_dst) {
#if TC_OK
    extern __shared__ char smem[];
    uint32_t sb = smem_to_u32(smem);
    int tid = threadIdx.x;
    int wid = tid >> 5;
    int lane = tid & 31;
    float* C = toExt ? Cext : (float*)g_buf1;

    int nCB = Nout >> 6;
    int nRows = (M + 127) >> 7;
    int nTiles = nRows * nCB;

    if (wid == 0) {
        TCGEN05_ALLOC(sb + SM_TMEM, 128);
        TCGEN05_RELINQ();
    }
    if (tid == 0) MBARRIER_INIT(sb + SM_MB0, 1);
    __syncthreads();
    uint32_t tmem;
    asm volatile("ld.shared.b32 %0, [%1];" : "=r"(tmem) : "r"(sb + SM_TMEM));

    // constant per-thread layout pieces
    int ar = tid & 127;
    bool a_hi = tid < 128;
    int a_off_base = (ar >> 3) * 1024 + (ar & 7) * 128;
    int a_sub = a_hi ? 0 : OFF_ALO;
    const __nv_bfloat16* a_arr = a_hi ? g_a_hi : g_a_lo;

    int rb = tid >> 1;
    int br = rb & 63;
    bool b_hi = rb < 64;
    const __nv_bfloat16* b_arr = b_hi ? g_wb_hi : g_wb_lo;
    int b_off_base = (br >> 3) * 1024 + (br & 7) * 128;
    int b_sub = b_hi ? OFF_BHI : OFF_BLO;
    int b_c0 = (tid & 1) * 4;

    auto load_stage = [&](int row0, int col0, int s) {
        uint32_t bufb = sb + SM_BUF;
        {
            const uint4* src = (const uint4*)(a_arr + (size_t)(row0 + ar) * 256 + s * 64);
            bool ok = (row0 + ar) < M;
#pragma unroll
            for (int c = 0; c < 8; c++) {
                int off = a_off_base + c * 16;
                off ^= (off >> 3) & 0x70;
                if (ok) CP_ASYNC16(bufb + a_sub + off, src + c);
                else *(uint4*)(smem + SM_BUF + a_sub + off) =
                         make_uint4(0u, 0u, 0u, 0u);
            }
        }
        {
            const uint4* src = (const uint4*)(b_arr + (size_t)(col0 + br) * 256 + s * 64);
#pragma unroll
            for (int q = 0; q < 4; q++) {
                int c = b_c0 + q;
                int off = b_off_base + c * 16;
                off ^= (off >> 3) & 0x70;
                CP_ASYNC16(bufb + b_sub + off, src + c);
            }
        }
        CP_COMMIT();
    };

    int mma_phase = 0;   // running mbarrier parity
    int t = blockIdx.x;
    if (t < nTiles) {
        load_stage((t / nCB) * 128, (t % nCB) * 64, 0);
    }

    for (; t < nTiles; t += GEMM_GRID) {
        int row0 = (t / nCB) * 128;
        int col0 = (t % nCB) * 64;
        int tn = t + GEMM_GRID;

#pragma unroll
        for (int s = 0; s < 4; s++) {
            CP_WAIT_GROUP(0);
            __syncthreads();
            asm volatile("fence.proxy.async.shared::cta;" ::: "memory");

            if (wid == 0) {
                if (elect_one_pred()) {
                    uint32_t bufb = sb + SM_BUF;
                    uint64_t dA_hi = make_desc(bufb);
                    uint64_t dA_lo = make_desc(bufb + OFF_ALO);
                    uint64_t dB_hi = make_desc(bufb + OFF_BHI);
                    uint64_t dB_lo = make_desc(bufb + OFF_BLO);
#pragma unroll
                    for (int term = 0; term < 3; term++) {
                        uint64_t da = (term == 2) ? dA_lo : dA_hi;
                        uint64_t db = (term == 1) ? dB_lo : dB_hi;
#pragma unroll
                        for (int kc = 0; kc < 4; kc++) {
                            mma_f16_ss(tmem, da + kc * 2, db + kc * 2, MMA_IDESC,
                                       !(s == 0 && term == 0 && kc == 0));
                        }
                    }
                    TCGEN05_COMMIT(sb + SM_MB0);
                }
            }
            // all threads wait for this stage's MMA: buffer then free
            MBARRIER_WAIT_PARITY(sb + SM_MB0, mma_phase & 1);
            mma_phase++;

            if (s < 3) {
                load_stage(row0, col0, s + 1);
            } else if (tn < nTiles) {
                load_stage((tn / nCB) * 128, (tn % nCB) * 64, 0);
            }
        }

        TCGEN05_FENCE_AFTER();

        // ---- epilogue: x16 chunks (low register pressure) ----
        if (wid < 4) {
            int r = row0 + wid * 32 + lane;
            float vs = 0.f, vd = 0.f;
#pragma unroll
            for (int ch = 0; ch < 4; ch++) {
                uint32_t d[16];
                TCGEN05_LD_32X32B_X16(d, tmem + ch * 16);
                TCGEN05_WAIT_LD();
                if (r < M) {
                    int cbase = col0 + ch * 16;
                    float cv[16];
#pragma unroll
                    for (int j = 0; j < 16; j++) {
                        cv[j] = __uint_as_float(d[j]);
                        if (bias) cv[j] += bias[cbase + j];
                    }
                    float* crow = C + (size_t)r * Nout + cbase;
#pragma unroll
                    for (int q = 0; q < 4; q++) {
                        *(float4*)(crow + q * 4) = make_float4(
                            cv[4 * q], cv[4 * q + 1], cv[4 * q + 2], cv[4 * q + 3]);
                    }
                    if (a_src) {
#pragma unroll
                        for (int j = 0; j < 16; j++) {
                            vs = fmaf(cv[j], a_src[cbase + j], vs);
                            vd = fmaf(cv[j], a_dst[cbase + j], vd);
                        }
                    }
                }
            }
            if (a_src && r < M) {
                int head = col0 >> 6;
                g_ssrc[r * 4 + head] = vs;
                g_sdst[r * 4 + head] = vd;
            }
            TCGEN05_FENCE_BEFORE();
        }
        __syncthreads();   // epilogue LDTMs done before next tile's MMA
    }

    __syncthreads();
    if (tid == 0)
        asm volatile("mbarrier.inval.shared.b64 [%0];" :: "r"(sb + SM_MB0) : "memory");
    if (wid == 0) TCGEN05_DEALLOC(tmem, 128);
#endif  // TC_OK
}

// ---------------- GAT aggregate + BN + ELU (chunked two-phase) ----------------
__global__ void __launch_bounds__(128)
gat_agg(const float* __restrict__ gamma, const float* __restrict__ beta,
        const float* __restrict__ mean, const float* __restrict__ var) {
    __shared__ float wgt[32][4];
    __shared__ int   sidx[32];
    __shared__ float smax[4];

    int n = blockIdx.x;
    int tid = threadIdx.x;
    int head = tid >> 5;
    int lane = tid & 31;
    int beg = g_rowbeg[n];
    int end = g_rowend[n];
    const float* hfeat = g_buf1;

    {
        float sd_h = g_sdst[n * 4 + head];
        float m = 0.f;
        for (int i = beg + lane; i < end; i += 32) {
            int s = g_csrc[i];
            float e = g_ssrc[s * 4 + head] + sd_h;
            e = (e >= 0.f) ? e : 0.2f * e;
            m = fmaxf(m, e);
        }
#pragma unroll
        for (int o = 16; o; o >>= 1) m = fmaxf(m, __shfl_xor_sync(~0u, m, o));
        if (lane == 0) smax[head] = m;
    }
    __syncthreads();

    int eh = tid & 3;
    int eo = tid >> 2;
    float sd_eh = g_sdst[n * 4 + eh];
    float m_eh = smax[eh];

    float acc0 = 0.f, acc1 = 0.f, ws = 0.f;
    int c = tid * 2;

    for (int base = beg; base < end; base += 32) {
        int cnt = min(32, end - base);
        {
            float w = 0.f;
            int s = -1;
            if (eo < cnt) {
                s = g_csrc[base + eo];
                float e = g_ssrc[s * 4 + eh] + sd_eh;
                e = (e >= 0.f) ? e : 0.2f * e;
                w = __expf(e - m_eh);
            }
            wgt[eo][eh] = w;
            if (eh == 0) sidx[eo] = s;
        }
        __syncthreads();
        for (int j = 0; j < cnt; j++) {
            float w = wgt[j][head];
            ws += w;
            float2 hv = *(const float2*)&hfeat[(size_t)sidx[j] * 256 + c];
            acc0 = fmaf(w, hv.x, acc0);
            acc1 = fmaf(w, hv.y, acc1);
        }
        __syncthreads();
    }

    float inv = 1.f / fmaxf(ws, 1e-9f);
    float o0 = acc0 * inv;
    float o1 = acc1 * inv;

    o0 = (o0 - mean[c]) * rsqrtf(var[c] + 1e-5f) * gamma[c] + beta[c];
    o1 = (o1 - mean[c + 1]) * rsqrtf(var[c + 1] + 1e-5f) * gamma[c + 1] + beta[c + 1];
    o0 = (o0 > 0.f) ? o0 : expm1f(o0);
    o1 = (o1 > 0.f) ? o1 : expm1f(o1);

    __nv_bfloat16 h0 = __float2bfloat16(o0);
    __nv_bfloat16 h1 = __float2bfloat16(o1);
    size_t idx2 = ((size_t)n * 256 + c) >> 1;
    ((__nv_bfloat162*)g_a_hi)[idx2] = __halves2bfloat162(h0, h1);
    ((__nv_bfloat162*)g_a_lo)[idx2] = __halves2bfloat162(
        __float2bfloat16(o0 - __bfloat162float(h0)),
        __float2bfloat16(o1 - __bfloat162float(h1)));
}

// ---------------------------------------------------------------------------
extern "C" void kernel_launch(void* const* d_in, const int* in_sizes, int n_in,
                              void* d_out, int out_size) {
    const float* x   = (const float*)d_in[0];
    const void*  ei  = d_in[1];
    const float* W1  = (const float*)d_in[2];
    const float* as1 = (const float*)d_in[3];
    const float* ad1 = (const float*)d_in[4];
    const float* g1  = (const float*)d_in[5];
    const float* b1  = (const float*)d_in[6];
    const float* m1  = (const float*)d_in[7];
    const float* v1  = (const float*)d_in[8];
    const float* W2  = (const float*)d_in[9];
    const float* as2 = (const float*)d_in[10];
    const float* ad2 = (const float*)d_in[11];
    const float* g2  = (const float*)d_in[12];
    const float* b2  = (const float*)d_in[13];
    const float* m2  = (const float*)d_in[14];
    const float* v2  = (const float*)d_in[15];
    const float* Wc  = (const float*)d_in[16];
    const float* bc  = (const float*)d_in[17];
    float* out = (float*)d_out;

    int N = in_sizes[0] / 256;
    int E = in_sizes[1] / 2;

    cudaFuncSetAttribute(gemm_tc, cudaFuncAttributeMaxDynamicSharedMemorySize,
                         SM_TOTAL);

    int nx2 = N * 128;
    int nw2 = 256 * 256 / 2;
    int nc2 = 64 * 256 / 2;

    // gemm_tc stays the 4th launch for ncu.
    conv_split_x<<<(nx2 + 255) / 256, 256>>>(x, nx2);              // 1
    conv_split_w<<<(nw2 + 255) / 256, 256>>>(W1, nw2);             // 2
    detect_dtype<<<1, 1>>>(ei, N);                                 // 3
    gemm_tc<<<GEMM_GRID, 256, SM_TOTAL>>>(nullptr, nullptr, 0, N, 256, as1, ad1); // 4
    zero_counts<<<(N + 255) / 256, 256>>>(N);                      // 5
    hist_kernel<<<(E + 255) / 256, 256>>>(ei, E, N);               // 6
    alloc_rows<<<(N + 1023) / 1024, 1024>>>(N);                    // 7
    scatter_kernel<<<(E + 255) / 256, 256>>>(ei, E, N);            // 8
    gat_agg<<<N, 128>>>(g1, b1, m1, v1);                           // 9

    // --- layer 2 ---
    conv_split_w<<<(nw2 + 255) / 256, 256>>>(W2, nw2);
    gemm_tc<<<GEMM_GRID, 256, SM_TOTAL>>>(nullptr, nullptr, 0, N, 256, as2, ad2);
    gat_agg<<<N, 128>>>(g2, b2, m2, v2);

    // --- classifier ---
    conv_split_w<<<(nc2 + 255) / 256, 256>>>(Wc, nc2);
    gemm_tc<<<GEMM_GRID, 256, SM_TOTAL>>>(bc, out, 1, N, 64, nullptr, nullptr);
}